// round 13
// baseline (speedup 1.0000x reference)
#include <cuda_runtime.h>
#include <cuda_bf16.h>
#include <cstdint>

// ============================================================================
// VQ-VAE quantizer, FUSED single main kernel (sm_100-safe: mma.sync+ldmatrix):
//  Stage A: bf16 HMMA approx of S=z.e -> per-row candidate set within hard
//           per-row margin (cross-lane min sharing, guarded insert,
//           recoverable overflow). Split accumulator chains for ILP.
//  Stage B (same block): bitwise-exact d2 on candidates (XLA tree norms +
//           sequential FMA dot), warp-cooperative exact fallback, outputs.
// Output layout (float32): [ z_q_st (8388608) | loss (1) | idx (131072) ]
// ============================================================================

#define N_ROWS 131072
#define D      64
#define K      2048
#define TM     128          // rows per block
#define KCH    256          // codes per smem chunk
#define NCHUNK (K / KCH)    // 8

// smem (bytes):
//  [0      .. 18432)   zbf bf16 [128][72] (stage A) -- reused as zs fp32 [128][65] (stage B)
//  [18432  .. 55296)   Bt buf0 bf16 [256][72]
//  [55296  .. 92160)   Bt buf1 bf16 [256][72]
//  [92160  .. 100352)  sse f32 [2048]
//  [100352 .. 104448)  s_ck int [128][8]            -- reused as sbidx via slot 0
//  [104448 .. 104960)  s_cnt int [128]
//  [104960 .. 104992)  lred f32 [8]
#define SM_ZBF   0
#define SM_BT0   18432
#define SM_BT1   55296
#define SM_SE    92160
#define SM_CK    100352
#define SM_CNT   104448
#define SM_LRED  104960
#define SMEM1    104992
#define BT_STRIDE 36864

__device__ float g_se[K];
__device__ float g_sz[N_ROWS];
__device__ float g_loss;
__device__ __align__(16) unsigned short g_eb[K * D];   // emb as bf16, row-major

// ---------------------------------------------------------------- helpers
__device__ __forceinline__ uint32_t smem_u32(const void* p) {
    uint32_t a;
    asm("{ .reg .u64 t; cvta.to.shared.u64 t, %1; cvt.u32.u64 %0, t; }"
        : "=r"(a) : "l"(p));
    return a;
}

__device__ __forceinline__ float tree32_sq(const float* __restrict__ x, int stride) {
    float l[32];
    #pragma unroll
    for (int t = 0; t < 32; t++) { float v = x[t * stride]; l[t] = __fmul_rn(v, v); }
    #pragma unroll
    for (int off = 16; off >= 1; off >>= 1)
        #pragma unroll
        for (int t = 0; t < 16; t++)
            if (t < off) l[t] = __fadd_rn(l[t], l[t + off]);
    return l[0];
}

__device__ __forceinline__ uint32_t pack_bf16x2(float lo, float hi) {
    __nv_bfloat162 h = __floats2bfloat162_rn(lo, hi);   // .x = lo half
    return *reinterpret_cast<uint32_t*>(&h);
}

// ---------------------------------------------------------------- prep
__global__ void zero_kernel() { g_loss = 0.0f; }

__global__ void prep_z_kernel(const float* __restrict__ z_e) {
    int r = blockIdx.x * 256 + threadIdx.x;
    const float* zr = z_e + (size_t)r * D;
    g_sz[r] = __fadd_rn(tree32_sq(zr, 1), tree32_sq(zr + 32, 1));
}

__global__ void prep_emb_kernel(const float* __restrict__ emb) {
    int gid = blockIdx.x * 256 + threadIdx.x;
    if (gid < K * D) {
        __nv_bfloat16 h = __float2bfloat16(emb[gid]);
        g_eb[gid] = *reinterpret_cast<unsigned short*>(&h);
    }
    if (gid < K)
        g_se[gid] = __fadd_rn(tree32_sq(emb + gid * D, 1),
                              tree32_sq(emb + gid * D + 32, 1));
}

// ---------------------------------------------------------------- fused main
// Insert: in-window iff VAL <= clim; slot stale iff cv > clim. Window update
// first. On slot exhaustion, record min dropped value (cdrop) — overflow is
// decided at the END against the final threshold (recoverable).
#define CAND_INS(S, VAL, KK)                                                   \
    do {                                                                       \
        if ((VAL) <= clim[S]) {                                                \
            if ((VAL) < crm[S]) { crm[S] = (VAL); clim[S] = (VAL) + msl[S]; }  \
            bool _ins = false;                                                 \
            _Pragma("unroll")                                                  \
            for (int _q = 0; _q < 2; _q++)                                     \
                if (!_ins && cv[S][_q] > clim[S]) {                            \
                    cv[S][_q] = (VAL); ck[S][_q] = (KK); _ins = true;          \
                }                                                              \
            if (!_ins) cdrop[S] = fminf(cdrop[S], (VAL));                      \
        }                                                                      \
    } while (0)

// async stage of one 256-code chunk (32 KB payload) into a Bt buffer
__device__ __forceinline__ void stage_chunk_async(uint32_t bt_smem, int ch, int tid) {
    const char* src = (const char*)g_eb + (size_t)ch * (KCH * 128);
    #pragma unroll
    for (int it = 0; it < 8; it++) {
        int i = tid + it * 256;
        int rr = i >> 3, j = i & 7;
        uint32_t dst = bt_smem + (uint32_t)(rr * 144 + j * 16);
        const char* s = src + rr * 128 + j * 16;
        asm volatile("cp.async.cg.shared.global [%0], [%1], 16;"
                     :: "r"(dst), "l"(s));
    }
    asm volatile("cp.async.commit_group;" ::: "memory");
}

__global__ __launch_bounds__(256, 2)
void vq_main(const float* __restrict__ z_e, const float* __restrict__ emb,
             float* __restrict__ out, int write_idx) {
    extern __shared__ char smem[];
    __nv_bfloat16* zbf = (__nv_bfloat16*)(smem + SM_ZBF);   // [128][72]
    float* sse  = (float*)(smem + SM_SE);
    int*   sck  = (int*)(smem + SM_CK);                     // [128][8]
    int*   scnt = (int*)(smem + SM_CNT);                    // [128]
    float* lred = (float*)(smem + SM_LRED);
    float* zs   = (float*)(smem + SM_ZBF);                  // [128][65] stage B

    const int tid = threadIdx.x;
    const int lane = tid & 31;
    const int wid = tid >> 5;
    const int rowbase = blockIdx.x * TM;

    const uint32_t bt0 = smem_u32(smem + SM_BT0);

    // kick off chunk 0 staging immediately
    stage_chunk_async(bt0, 0, tid);

    // ================= stage A: approx GEMM + candidate windows =============
    for (int i = tid; i < TM * 16; i += 256) {
        int r = i >> 4, c = (i & 15) * 4;
        float4 v = *(const float4*)(z_e + (size_t)(rowbase + r) * D + c);
        *(uint32_t*)&zbf[r * 72 + c]     = pack_bf16x2(v.x, v.y);
        *(uint32_t*)&zbf[r * 72 + c + 2] = pack_bf16x2(v.z, v.w);
    }
    for (int i = tid; i < K; i += 256) sse[i] = g_se[i];
    __syncthreads();

    // A fragments (held through stage A): warp = 16-row stripe
    const int r0 = wid * 16 + (lane >> 2);
    const int k0 = (lane & 3) * 2;
    uint32_t a[4][4];
    #pragma unroll
    for (int ks = 0; ks < 4; ks++) {
        a[ks][0] = *(uint32_t*)&zbf[r0 * 72 + ks * 16 + k0];
        a[ks][1] = *(uint32_t*)&zbf[(r0 + 8) * 72 + ks * 16 + k0];
        a[ks][2] = *(uint32_t*)&zbf[r0 * 72 + ks * 16 + k0 + 8];
        a[ks][3] = *(uint32_t*)&zbf[(r0 + 8) * 72 + ks * 16 + k0 + 8];
    }

    float msl[2];
    msl[0] = __fmaf_rn(sqrtf(g_sz[rowbase + r0]),     3.1e-5f, 2.0e-5f);
    msl[1] = __fmaf_rn(sqrtf(g_sz[rowbase + r0 + 8]), 3.1e-5f, 2.0e-5f);

    float cv[2][2]; int ck[2][2];
    float crm[2], clim[2], cdrop[2];
    #pragma unroll
    for (int s = 0; s < 2; s++) {
        crm[s] = 3.4e38f; clim[s] = 3.4e38f; cdrop[s] = 3.4e38f;
        #pragma unroll
        for (int q = 0; q < 2; q++) { cv[s][q] = 3.4e38f; ck[s][q] = 0; }
    }

    const uint32_t lmoff = (uint32_t)(((lane & 7) * 72 + (lane >> 3) * 8) * 2);

    for (int ch = 0; ch < NCHUNK; ch++) {
        asm volatile("cp.async.wait_group 0;" ::: "memory");
        __syncthreads();   // chunk ch data visible; prev compute done everywhere
        if (ch + 1 < NCHUNK)
            stage_chunk_async(bt0 + (uint32_t)(((ch + 1) & 1) * BT_STRIDE),
                              ch + 1, tid);

        const uint32_t bbase = bt0 + (uint32_t)((ch & 1) * BT_STRIDE) + lmoff;

        #pragma unroll 4
        for (int nt = 0; nt < 32; nt++) {
            uint32_t b[8];
            uint32_t addr = bbase + (uint32_t)(nt * 8 * 144);
            asm volatile(
                "ldmatrix.sync.aligned.m8n8.x4.shared.b16 {%0,%1,%2,%3}, [%4];"
                : "=r"(b[0]), "=r"(b[1]), "=r"(b[2]), "=r"(b[3]) : "r"(addr));
            asm volatile(
                "ldmatrix.sync.aligned.m8n8.x4.shared.b16 {%0,%1,%2,%3}, [%4];"
                : "=r"(b[4]), "=r"(b[5]), "=r"(b[6]), "=r"(b[7]) : "r"(addr + 64));

            // two independent 2-deep HMMA chains (split accumulators)
            float c01[4] = {0.f, 0.f, 0.f, 0.f};
            float c23[4] = {0.f, 0.f, 0.f, 0.f};
            #pragma unroll
            for (int ks = 0; ks < 2; ks++) {
                asm volatile(
                    "mma.sync.aligned.m16n8k16.row.col.f32.bf16.bf16.f32 "
                    "{%0,%1,%2,%3}, {%4,%5,%6,%7}, {%8,%9}, {%0,%1,%2,%3};"
                    : "+f"(c01[0]), "+f"(c01[1]), "+f"(c01[2]), "+f"(c01[3])
                    : "r"(a[ks][0]), "r"(a[ks][1]), "r"(a[ks][2]), "r"(a[ks][3]),
                      "r"(b[ks * 2]), "r"(b[ks * 2 + 1]));
            }
            #pragma unroll
            for (int ks = 2; ks < 4; ks++) {
                asm volatile(
                    "mma.sync.aligned.m16n8k16.row.col.f32.bf16.bf16.f32 "
                    "{%0,%1,%2,%3}, {%4,%5,%6,%7}, {%8,%9}, {%0,%1,%2,%3};"
                    : "+f"(c23[0]), "+f"(c23[1]), "+f"(c23[2]), "+f"(c23[3])
                    : "r"(a[ks][0]), "r"(a[ks][1]), "r"(a[ks][2]), "r"(a[ks][3]),
                      "r"(b[ks * 2]), "r"(b[ks * 2 + 1]));
            }
            const int colg = ch * KCH + nt * 8 + k0;
            float2 se2 = *(const float2*)&sse[colg];
            float v00 = fmaf(c01[0] + c23[0], -2.0f, se2.x);
            float v01 = fmaf(c01[1] + c23[1], -2.0f, se2.y);
            float v10 = fmaf(c01[2] + c23[2], -2.0f, se2.x);
            float v11 = fmaf(c01[3] + c23[3], -2.0f, se2.y);
            float m0 = fminf(v00, v01);
            float m1 = fminf(v10, v11);
            if (fminf(m0, m1) <= fmaxf(clim[0], clim[1])) {
                if (m0 <= clim[0]) {
                    CAND_INS(0, v00, colg);
                    CAND_INS(0, v01, colg + 1);
                }
                if (m1 <= clim[1]) {
                    CAND_INS(1, v10, colg);
                    CAND_INS(1, v11, colg + 1);
                }
            }
        }

        #pragma unroll
        for (int s = 0; s < 2; s++) {
            float gm = crm[s];
            gm = fminf(gm, __shfl_xor_sync(0xffffffffu, gm, 1));
            gm = fminf(gm, __shfl_xor_sync(0xffffffffu, gm, 2));
            if (gm < crm[s]) { crm[s] = gm; clim[s] = gm + msl[s]; }
        }
    }
    __syncthreads();   // stage A shared reads done (zbf/Bt0 become dead)

    // ---- stage z fp32 into smem (reuses zbf/Bt0 space), coalesced ----
    for (int i = tid; i < TM * D; i += 256) {
        zs[(i >> 6) * 65 + (i & 63)] = z_e[(size_t)rowbase * D + i];
    }

    // ---- merge candidates across the 4 lanes per row -> smem lists ----
    const int lq = lane & 3;
    #pragma unroll
    for (int s = 0; s < 2; s++) {
        float gm = crm[s];
        gm = fminf(gm, __shfl_xor_sync(0xffffffffu, gm, 1));
        gm = fminf(gm, __shfl_xor_sync(0xffffffffu, gm, 2));
        float thr = gm + msl[s];
        int cl = 0;
        #pragma unroll
        for (int q = 0; q < 2; q++) if (cv[s][q] <= thr) cl++;
        int o = (cdrop[s] <= thr) ? 1 : 0;
        o |= __shfl_xor_sync(0xffffffffu, o, 1);
        o |= __shfl_xor_sync(0xffffffffu, o, 2);
        int base = lane & ~3;
        int c0 = __shfl_sync(0xffffffffu, cl, base);
        int c1 = __shfl_sync(0xffffffffu, cl, base + 1);
        int c2 = __shfl_sync(0xffffffffu, cl, base + 2);
        int c3 = __shfl_sync(0xffffffffu, cl, base + 3);
        int tot = c0 + c1 + c2 + c3;           // <= 8 by construction
        int off = (lq > 0 ? c0 : 0) + (lq > 1 ? c1 : 0) + (lq > 2 ? c2 : 0);
        int lrow = wid * 16 + (lane >> 2) + s * 8;   // row within block
        if (o) {
            if (lq == 0) scnt[lrow] = 10000;
        } else {
            if (lq == 0) scnt[lrow] = tot;
            int w = 0;
            #pragma unroll
            for (int q = 0; q < 2; q++)
                if (cv[s][q] <= thr) { sck[lrow * 8 + off + w] = ck[s][q]; w++; }
        }
    }
    __syncthreads();

    // ================= stage B: exact resolution (warps 0-3) ================
    int bi = 0x7fffffff;
    if (tid < TM) {
        const float* zr = &zs[tid * 65];
        const float A = g_sz[rowbase + tid];
        const int cnt = scnt[tid];
        float best = 3.4e38f;
        const bool ovf = cnt > 8;

        if (!ovf) {
            for (int i = 0; i < cnt; i++) {
                int k = sck[tid * 8 + i];
                const float* ep = emb + k * D;
                float B = 0.0f;
                #pragma unroll
                for (int d = 0; d < D; d++) B = __fmaf_rn(zr[d], ep[d], B);
                float d2 = __fadd_rn(__fsub_rn(A, __fmul_rn(2.0f, B)), sse[k]);
                if (d2 < best || (d2 == best && k < bi)) { best = d2; bi = k; }
            }
        }

        // warp-cooperative exact fallback for overflow rows (rare)
        unsigned m = __ballot_sync(0xffffffffu, ovf);
        while (m) {
            int r = __ffs(m) - 1;
            m &= m - 1;
            const float* zrr = &zs[(wid * 32 + r) * 65];
            float Ar = g_sz[rowbase + wid * 32 + r];
            float wb = 3.4e38f;
            int wbi = 0x7fffffff;
            for (int k = lane; k < K; k += 32) {
                const float* ep = emb + k * D;
                float B = 0.0f;
                #pragma unroll
                for (int d = 0; d < D; d++) B = __fmaf_rn(zrr[d], ep[d], B);
                float d2 = __fadd_rn(__fsub_rn(Ar, __fmul_rn(2.0f, B)), sse[k]);
                if (d2 < wb || (d2 == wb && k < wbi)) { wb = d2; wbi = k; }
            }
            #pragma unroll
            for (int off = 16; off >= 1; off >>= 1) {
                float ov = __shfl_xor_sync(0xffffffffu, wb, off);
                int   oi = __shfl_xor_sync(0xffffffffu, wbi, off);
                if (ov < wb || (ov == wb && oi < wbi)) { wb = ov; wbi = oi; }
            }
            if (lane == r) bi = wbi;
        }
    }
    __syncthreads();              // all candidate-list reads done
    if (tid < TM) sck[tid] = bi;  // sbidx reuses sck slot 0..127
    __syncthreads();

    // ---- coalesced gather + straight-through output + loss (all 256) ----
    float lacc = 0.0f;
    for (int i = tid; i < TM * D; i += 256) {
        int r = i >> 6, d = i & 63;
        int b = sck[r];
        float q = emb[b * D + d];
        float z = zs[r * 65 + d];
        float diff = __fsub_rn(q, z);
        out[(size_t)rowbase * D + i] = __fadd_rn(z, diff);
        lacc = __fmaf_rn(diff, diff, lacc);
    }
    if (write_idx && tid < TM)
        out[(size_t)N_ROWS * D + 1 + rowbase + tid] = (float)sck[tid];

    #pragma unroll
    for (int mm = 16; mm >= 1; mm >>= 1)
        lacc += __shfl_xor_sync(0xffffffffu, lacc, mm);
    if (lane == 0) lred[wid] = lacc;
    __syncthreads();
    if (tid == 0) {
        float s = 0.0f;
        #pragma unroll
        for (int w = 0; w < 8; w++) s += lred[w];
        atomicAdd(&g_loss, s);
    }
}

__global__ void finalize_kernel(float* __restrict__ out, int write_loss) {
    if (write_loss) {
        float m = g_loss / 8388608.0f;
        out[(size_t)N_ROWS * D] = __fadd_rn(__fmul_rn(0.25f, m), m);
    }
}

// ---------------------------------------------------------------- launch
extern "C" void kernel_launch(void* const* d_in, const int* in_sizes, int n_in,
                              void* d_out, int out_size) {
    const float* z_e = (const float*)d_in[0];
    const float* emb = (const float*)d_in[1];
    float* out = (float*)d_out;

    cudaFuncSetAttribute(vq_main, cudaFuncAttributeMaxDynamicSharedMemorySize, SMEM1);

    int write_loss = (out_size > N_ROWS * D) ? 1 : 0;
    int write_idx  = (out_size >= N_ROWS * D + 1 + N_ROWS) ? 1 : 0;

    zero_kernel<<<1, 1>>>();                                   // launch 0
    prep_z_kernel<<<N_ROWS / 256, 256>>>(z_e);                 // launch 1
    prep_emb_kernel<<<(K * D) / 256, 256>>>(emb);              // launch 2
    vq_main<<<N_ROWS / TM, 256, SMEM1>>>(z_e, emb, out, write_idx); // launch 3 (ncu)
    finalize_kernel<<<1, 1>>>(out, write_loss);                // launch 4
}

// round 14
// speedup vs baseline: 2.1487x; 2.1487x over previous
#include <cuda_runtime.h>
#include <cuda_bf16.h>
#include <cstdint>

// ============================================================================
// VQ-VAE quantizer, FUSED single main kernel (sm_100-safe: mma.sync+ldmatrix):
//  Stage A: bf16 HMMA approx of S=z.e -> per-row candidate set within hard
//           per-row margin (cross-lane min sharing, guarded insert,
//           recoverable overflow, 4 slots/lane). Split accumulator chains.
//  Stage B (same block): bitwise-exact d2 on candidates (XLA tree norms +
//           sequential FMA dot), warp-cooperative exact fallback, outputs.
// Output layout (float32): [ z_q_st (8388608) | loss (1) | idx (131072) ]
// ============================================================================

#define N_ROWS 131072
#define D      64
#define K      2048
#define TM     128          // rows per block
#define KCH    256          // codes per smem chunk
#define NCHUNK (K / KCH)    // 8

// smem (bytes):
//  [0      .. 18432)   zbf bf16 [128][72] (stage A) -- reused as zs fp32 [128][65] (stage B)
//  [18432  .. 55296)   Bt buf0 bf16 [256][72]
//  [55296  .. 92160)   Bt buf1 bf16 [256][72]
//  [92160  .. 100352)  sse f32 [2048]
//  [100352 .. 104448)  s_ck int [128][8]            -- reused as sbidx via slot 0
//  [104448 .. 104960)  s_cnt int [128]
//  [104960 .. 104992)  lred f32 [8]
#define SM_ZBF   0
#define SM_BT0   18432
#define SM_BT1   55296
#define SM_SE    92160
#define SM_CK    100352
#define SM_CNT   104448
#define SM_LRED  104960
#define SMEM1    104992
#define BT_STRIDE 36864

__device__ float g_se[K];
__device__ float g_sz[N_ROWS];
__device__ float g_loss;
__device__ __align__(16) unsigned short g_eb[K * D];   // emb as bf16, row-major

// ---------------------------------------------------------------- helpers
__device__ __forceinline__ uint32_t smem_u32(const void* p) {
    uint32_t a;
    asm("{ .reg .u64 t; cvta.to.shared.u64 t, %1; cvt.u32.u64 %0, t; }"
        : "=r"(a) : "l"(p));
    return a;
}

__device__ __forceinline__ float tree32_sq(const float* __restrict__ x, int stride) {
    float l[32];
    #pragma unroll
    for (int t = 0; t < 32; t++) { float v = x[t * stride]; l[t] = __fmul_rn(v, v); }
    #pragma unroll
    for (int off = 16; off >= 1; off >>= 1)
        #pragma unroll
        for (int t = 0; t < 16; t++)
            if (t < off) l[t] = __fadd_rn(l[t], l[t + off]);
    return l[0];
}

__device__ __forceinline__ uint32_t pack_bf16x2(float lo, float hi) {
    __nv_bfloat162 h = __floats2bfloat162_rn(lo, hi);   // .x = lo half
    return *reinterpret_cast<uint32_t*>(&h);
}

// ---------------------------------------------------------------- prep
__global__ void zero_kernel() { g_loss = 0.0f; }

__global__ void prep_z_kernel(const float* __restrict__ z_e) {
    int r = blockIdx.x * 256 + threadIdx.x;
    const float* zr = z_e + (size_t)r * D;
    g_sz[r] = __fadd_rn(tree32_sq(zr, 1), tree32_sq(zr + 32, 1));
}

__global__ void prep_emb_kernel(const float* __restrict__ emb) {
    int gid = blockIdx.x * 256 + threadIdx.x;
    if (gid < K * D) {
        __nv_bfloat16 h = __float2bfloat16(emb[gid]);
        g_eb[gid] = *reinterpret_cast<unsigned short*>(&h);
    }
    if (gid < K)
        g_se[gid] = __fadd_rn(tree32_sq(emb + gid * D, 1),
                              tree32_sq(emb + gid * D + 32, 1));
}

// ---------------------------------------------------------------- fused main
// Insert: in-window iff VAL <= clim; slot stale iff cv > clim. Window update
// first. On slot exhaustion, record min dropped value (cdrop) — overflow is
// decided at the END against the final threshold (recoverable). 4 slots/lane:
// measured necessary to keep the exact-fallback rate negligible (R13 showed a
// 2.1x regression at 2 slots).
#define CAND_INS(S, VAL, KK)                                                   \
    do {                                                                       \
        if ((VAL) <= clim[S]) {                                                \
            if ((VAL) < crm[S]) { crm[S] = (VAL); clim[S] = (VAL) + msl[S]; }  \
            bool _ins = false;                                                 \
            _Pragma("unroll")                                                  \
            for (int _q = 0; _q < 4; _q++)                                     \
                if (!_ins && cv[S][_q] > clim[S]) {                            \
                    cv[S][_q] = (VAL); ck[S][_q] = (KK); _ins = true;          \
                }                                                              \
            if (!_ins) cdrop[S] = fminf(cdrop[S], (VAL));                      \
        }                                                                      \
    } while (0)

// async stage of one 256-code chunk (32 KB payload) into a Bt buffer
__device__ __forceinline__ void stage_chunk_async(uint32_t bt_smem, int ch, int tid) {
    const char* src = (const char*)g_eb + (size_t)ch * (KCH * 128);
    #pragma unroll
    for (int it = 0; it < 8; it++) {
        int i = tid + it * 256;
        int rr = i >> 3, j = i & 7;
        uint32_t dst = bt_smem + (uint32_t)(rr * 144 + j * 16);
        const char* s = src + rr * 128 + j * 16;
        asm volatile("cp.async.cg.shared.global [%0], [%1], 16;"
                     :: "r"(dst), "l"(s));
    }
    asm volatile("cp.async.commit_group;" ::: "memory");
}

__global__ __launch_bounds__(256, 2)
void vq_main(const float* __restrict__ z_e, const float* __restrict__ emb,
             float* __restrict__ out, int write_idx) {
    extern __shared__ char smem[];
    __nv_bfloat16* zbf = (__nv_bfloat16*)(smem + SM_ZBF);   // [128][72]
    float* sse  = (float*)(smem + SM_SE);
    int*   sck  = (int*)(smem + SM_CK);                     // [128][8]
    int*   scnt = (int*)(smem + SM_CNT);                    // [128]
    float* lred = (float*)(smem + SM_LRED);
    float* zs   = (float*)(smem + SM_ZBF);                  // [128][65] stage B

    const int tid = threadIdx.x;
    const int lane = tid & 31;
    const int wid = tid >> 5;
    const int rowbase = blockIdx.x * TM;

    const uint32_t bt0 = smem_u32(smem + SM_BT0);

    // kick off chunk 0 staging immediately
    stage_chunk_async(bt0, 0, tid);

    // ================= stage A: approx GEMM + candidate windows =============
    for (int i = tid; i < TM * 16; i += 256) {
        int r = i >> 4, c = (i & 15) * 4;
        float4 v = *(const float4*)(z_e + (size_t)(rowbase + r) * D + c);
        *(uint32_t*)&zbf[r * 72 + c]     = pack_bf16x2(v.x, v.y);
        *(uint32_t*)&zbf[r * 72 + c + 2] = pack_bf16x2(v.z, v.w);
    }
    for (int i = tid; i < K; i += 256) sse[i] = g_se[i];
    __syncthreads();

    // A fragments (held through stage A): warp = 16-row stripe
    const int r0 = wid * 16 + (lane >> 2);
    const int k0 = (lane & 3) * 2;
    uint32_t a[4][4];
    #pragma unroll
    for (int ks = 0; ks < 4; ks++) {
        a[ks][0] = *(uint32_t*)&zbf[r0 * 72 + ks * 16 + k0];
        a[ks][1] = *(uint32_t*)&zbf[(r0 + 8) * 72 + ks * 16 + k0];
        a[ks][2] = *(uint32_t*)&zbf[r0 * 72 + ks * 16 + k0 + 8];
        a[ks][3] = *(uint32_t*)&zbf[(r0 + 8) * 72 + ks * 16 + k0 + 8];
    }

    float msl[2];
    msl[0] = __fmaf_rn(sqrtf(g_sz[rowbase + r0]),     3.1e-5f, 2.0e-5f);
    msl[1] = __fmaf_rn(sqrtf(g_sz[rowbase + r0 + 8]), 3.1e-5f, 2.0e-5f);

    float cv[2][4]; int ck[2][4];
    float crm[2], clim[2], cdrop[2];
    #pragma unroll
    for (int s = 0; s < 2; s++) {
        crm[s] = 3.4e38f; clim[s] = 3.4e38f; cdrop[s] = 3.4e38f;
        #pragma unroll
        for (int q = 0; q < 4; q++) { cv[s][q] = 3.4e38f; ck[s][q] = 0; }
    }

    const uint32_t lmoff = (uint32_t)(((lane & 7) * 72 + (lane >> 3) * 8) * 2);

    for (int ch = 0; ch < NCHUNK; ch++) {
        asm volatile("cp.async.wait_group 0;" ::: "memory");
        __syncthreads();   // chunk ch data visible; prev compute done everywhere
        if (ch + 1 < NCHUNK)
            stage_chunk_async(bt0 + (uint32_t)(((ch + 1) & 1) * BT_STRIDE),
                              ch + 1, tid);

        const uint32_t bbase = bt0 + (uint32_t)((ch & 1) * BT_STRIDE) + lmoff;

        #pragma unroll 4
        for (int nt = 0; nt < 32; nt++) {
            uint32_t b[8];
            uint32_t addr = bbase + (uint32_t)(nt * 8 * 144);
            asm volatile(
                "ldmatrix.sync.aligned.m8n8.x4.shared.b16 {%0,%1,%2,%3}, [%4];"
                : "=r"(b[0]), "=r"(b[1]), "=r"(b[2]), "=r"(b[3]) : "r"(addr));
            asm volatile(
                "ldmatrix.sync.aligned.m8n8.x4.shared.b16 {%0,%1,%2,%3}, [%4];"
                : "=r"(b[4]), "=r"(b[5]), "=r"(b[6]), "=r"(b[7]) : "r"(addr + 64));

            // two independent 2-deep HMMA chains (split accumulators)
            float c01[4] = {0.f, 0.f, 0.f, 0.f};
            float c23[4] = {0.f, 0.f, 0.f, 0.f};
            #pragma unroll
            for (int ks = 0; ks < 2; ks++) {
                asm volatile(
                    "mma.sync.aligned.m16n8k16.row.col.f32.bf16.bf16.f32 "
                    "{%0,%1,%2,%3}, {%4,%5,%6,%7}, {%8,%9}, {%0,%1,%2,%3};"
                    : "+f"(c01[0]), "+f"(c01[1]), "+f"(c01[2]), "+f"(c01[3])
                    : "r"(a[ks][0]), "r"(a[ks][1]), "r"(a[ks][2]), "r"(a[ks][3]),
                      "r"(b[ks * 2]), "r"(b[ks * 2 + 1]));
            }
            #pragma unroll
            for (int ks = 2; ks < 4; ks++) {
                asm volatile(
                    "mma.sync.aligned.m16n8k16.row.col.f32.bf16.bf16.f32 "
                    "{%0,%1,%2,%3}, {%4,%5,%6,%7}, {%8,%9}, {%0,%1,%2,%3};"
                    : "+f"(c23[0]), "+f"(c23[1]), "+f"(c23[2]), "+f"(c23[3])
                    : "r"(a[ks][0]), "r"(a[ks][1]), "r"(a[ks][2]), "r"(a[ks][3]),
                      "r"(b[ks * 2]), "r"(b[ks * 2 + 1]));
            }
            const int colg = ch * KCH + nt * 8 + k0;
            float2 se2 = *(const float2*)&sse[colg];
            float v00 = fmaf(c01[0] + c23[0], -2.0f, se2.x);
            float v01 = fmaf(c01[1] + c23[1], -2.0f, se2.y);
            float v10 = fmaf(c01[2] + c23[2], -2.0f, se2.x);
            float v11 = fmaf(c01[3] + c23[3], -2.0f, se2.y);
            float m0 = fminf(v00, v01);
            float m1 = fminf(v10, v11);
            if (fminf(m0, m1) <= fmaxf(clim[0], clim[1])) {
                if (m0 <= clim[0]) {
                    CAND_INS(0, v00, colg);
                    CAND_INS(0, v01, colg + 1);
                }
                if (m1 <= clim[1]) {
                    CAND_INS(1, v10, colg);
                    CAND_INS(1, v11, colg + 1);
                }
            }
        }

        #pragma unroll
        for (int s = 0; s < 2; s++) {
            float gm = crm[s];
            gm = fminf(gm, __shfl_xor_sync(0xffffffffu, gm, 1));
            gm = fminf(gm, __shfl_xor_sync(0xffffffffu, gm, 2));
            if (gm < crm[s]) { crm[s] = gm; clim[s] = gm + msl[s]; }
        }
    }
    __syncthreads();   // stage A shared reads done (zbf/Bt0 become dead)

    // ---- stage z fp32 into smem (reuses zbf/Bt0 space), coalesced ----
    for (int i = tid; i < TM * D; i += 256) {
        zs[(i >> 6) * 65 + (i & 63)] = z_e[(size_t)rowbase * D + i];
    }

    // ---- merge candidates across the 4 lanes per row -> smem lists ----
    const int lq = lane & 3;
    #pragma unroll
    for (int s = 0; s < 2; s++) {
        float gm = crm[s];
        gm = fminf(gm, __shfl_xor_sync(0xffffffffu, gm, 1));
        gm = fminf(gm, __shfl_xor_sync(0xffffffffu, gm, 2));
        float thr = gm + msl[s];
        int cl = 0;
        #pragma unroll
        for (int q = 0; q < 4; q++) if (cv[s][q] <= thr) cl++;
        int o = (cdrop[s] <= thr) ? 1 : 0;
        o |= __shfl_xor_sync(0xffffffffu, o, 1);
        o |= __shfl_xor_sync(0xffffffffu, o, 2);
        int base = lane & ~3;
        int c0 = __shfl_sync(0xffffffffu, cl, base);
        int c1 = __shfl_sync(0xffffffffu, cl, base + 1);
        int c2 = __shfl_sync(0xffffffffu, cl, base + 2);
        int c3 = __shfl_sync(0xffffffffu, cl, base + 3);
        int tot = c0 + c1 + c2 + c3;
        int off = (lq > 0 ? c0 : 0) + (lq > 1 ? c1 : 0) + (lq > 2 ? c2 : 0);
        int lrow = wid * 16 + (lane >> 2) + s * 8;   // row within block
        if (tot > 8 || o) {
            if (lq == 0) scnt[lrow] = 10000;
        } else {
            if (lq == 0) scnt[lrow] = tot;
            int w = 0;
            #pragma unroll
            for (int q = 0; q < 4; q++)
                if (cv[s][q] <= thr) { sck[lrow * 8 + off + w] = ck[s][q]; w++; }
        }
    }
    __syncthreads();

    // ================= stage B: exact resolution (warps 0-3) ================
    int bi = 0x7fffffff;
    if (tid < TM) {
        const float* zr = &zs[tid * 65];
        const float A = g_sz[rowbase + tid];
        const int cnt = scnt[tid];
        float best = 3.4e38f;
        const bool ovf = cnt > 8;

        if (!ovf) {
            for (int i = 0; i < cnt; i++) {
                int k = sck[tid * 8 + i];
                const float* ep = emb + k * D;
                float B = 0.0f;
                #pragma unroll
                for (int d = 0; d < D; d++) B = __fmaf_rn(zr[d], ep[d], B);
                float d2 = __fadd_rn(__fsub_rn(A, __fmul_rn(2.0f, B)), sse[k]);
                if (d2 < best || (d2 == best && k < bi)) { best = d2; bi = k; }
            }
        }

        // warp-cooperative exact fallback for overflow rows (rare)
        unsigned m = __ballot_sync(0xffffffffu, ovf);
        while (m) {
            int r = __ffs(m) - 1;
            m &= m - 1;
            const float* zrr = &zs[(wid * 32 + r) * 65];
            float Ar = g_sz[rowbase + wid * 32 + r];
            float wb = 3.4e38f;
            int wbi = 0x7fffffff;
            for (int k = lane; k < K; k += 32) {
                const float* ep = emb + k * D;
                float B = 0.0f;
                #pragma unroll
                for (int d = 0; d < D; d++) B = __fmaf_rn(zrr[d], ep[d], B);
                float d2 = __fadd_rn(__fsub_rn(Ar, __fmul_rn(2.0f, B)), sse[k]);
                if (d2 < wb || (d2 == wb && k < wbi)) { wb = d2; wbi = k; }
            }
            #pragma unroll
            for (int off = 16; off >= 1; off >>= 1) {
                float ov = __shfl_xor_sync(0xffffffffu, wb, off);
                int   oi = __shfl_xor_sync(0xffffffffu, wbi, off);
                if (ov < wb || (ov == wb && oi < wbi)) { wb = ov; wbi = oi; }
            }
            if (lane == r) bi = wbi;
        }
    }
    __syncthreads();              // all candidate-list reads done
    if (tid < TM) sck[tid] = bi;  // sbidx reuses sck slot 0..127
    __syncthreads();

    // ---- coalesced gather + straight-through output + loss (all 256) ----
    float lacc = 0.0f;
    for (int i = tid; i < TM * D; i += 256) {
        int r = i >> 6, d = i & 63;
        int b = sck[r];
        float q = emb[b * D + d];
        float z = zs[r * 65 + d];
        float diff = __fsub_rn(q, z);
        out[(size_t)rowbase * D + i] = __fadd_rn(z, diff);
        lacc = __fmaf_rn(diff, diff, lacc);
    }
    if (write_idx && tid < TM)
        out[(size_t)N_ROWS * D + 1 + rowbase + tid] = (float)sck[tid];

    #pragma unroll
    for (int mm = 16; mm >= 1; mm >>= 1)
        lacc += __shfl_xor_sync(0xffffffffu, lacc, mm);
    if (lane == 0) lred[wid] = lacc;
    __syncthreads();
    if (tid == 0) {
        float s = 0.0f;
        #pragma unroll
        for (int w = 0; w < 8; w++) s += lred[w];
        atomicAdd(&g_loss, s);
    }
}

__global__ void finalize_kernel(float* __restrict__ out, int write_loss) {
    if (write_loss) {
        float m = g_loss / 8388608.0f;
        out[(size_t)N_ROWS * D] = __fadd_rn(__fmul_rn(0.25f, m), m);
    }
}

// ---------------------------------------------------------------- launch
extern "C" void kernel_launch(void* const* d_in, const int* in_sizes, int n_in,
                              void* d_out, int out_size) {
    const float* z_e = (const float*)d_in[0];
    const float* emb = (const float*)d_in[1];
    float* out = (float*)d_out;

    cudaFuncSetAttribute(vq_main, cudaFuncAttributeMaxDynamicSharedMemorySize, SMEM1);

    int write_loss = (out_size > N_ROWS * D) ? 1 : 0;
    int write_idx  = (out_size >= N_ROWS * D + 1 + N_ROWS) ? 1 : 0;

    zero_kernel<<<1, 1>>>();                                   // launch 0
    prep_z_kernel<<<N_ROWS / 256, 256>>>(z_e);                 // launch 1
    prep_emb_kernel<<<(K * D) / 256, 256>>>(emb);              // launch 2
    vq_main<<<N_ROWS / TM, 256, SMEM1>>>(z_e, emb, out, write_idx); // launch 3 (ncu)
    finalize_kernel<<<1, 1>>>(out, write_loss);                // launch 4
}

// round 15
// speedup vs baseline: 2.3077x; 1.0740x over previous
#include <cuda_runtime.h>
#include <cuda_bf16.h>
#include <cstdint>

// ============================================================================
// VQ-VAE quantizer, FUSED single main kernel (sm_100-safe: mma.sync+ldmatrix):
//  Stage A: bf16 HMMA approx of S=z.e -> per-row candidate set within hard
//           per-row margin (cross-lane min sharing, guarded insert,
//           recoverable overflow, 4 slots/lane).
//  Stage B (same block): bitwise-exact d2 on candidates (XLA tree norms +
//           sequential FMA dot), warp-cooperative exact fallback, outputs.
//  This round: 3 CTAs/SM (single-buffered Bt, reg-trimmed mainloop).
// Output layout (float32): [ z_q_st (8388608) | loss (1) | idx (131072) ]
// ============================================================================

#define N_ROWS 131072
#define D      64
#define K      2048
#define TM     128          // rows per block
#define KCH    256          // codes per smem chunk
#define NCHUNK (K / KCH)    // 8

// smem (bytes):
//  [0      .. 18432)   zbf bf16 [128][72] (stage A) -- reused as zs fp32 [128][65] (stage B)
//  [18432  .. 55296)   Bt bf16 [256][72]
//  [55296  .. 63488)   sse f32 [2048]
//  [63488  .. 67584)   s_ck int [128][8]            -- reused as sbidx via slot 0
//  [67584  .. 68096)   s_cnt int [128]
//  [68096  .. 68128)   lred f32 [8]
#define SM_ZBF   0
#define SM_BT    18432
#define SM_SE    55296
#define SM_CK    63488
#define SM_CNT   67584
#define SM_LRED  68096
#define SMEM1    68128

__device__ float g_se[K];
__device__ float g_sz[N_ROWS];
__device__ float g_loss;
__device__ __align__(16) unsigned short g_eb[K * D];   // emb as bf16, row-major

// ---------------------------------------------------------------- helpers
__device__ __forceinline__ uint32_t smem_u32(const void* p) {
    uint32_t a;
    asm("{ .reg .u64 t; cvta.to.shared.u64 t, %1; cvt.u32.u64 %0, t; }"
        : "=r"(a) : "l"(p));
    return a;
}

__device__ __forceinline__ float tree32_sq(const float* __restrict__ x, int stride) {
    float l[32];
    #pragma unroll
    for (int t = 0; t < 32; t++) { float v = x[t * stride]; l[t] = __fmul_rn(v, v); }
    #pragma unroll
    for (int off = 16; off >= 1; off >>= 1)
        #pragma unroll
        for (int t = 0; t < 16; t++)
            if (t < off) l[t] = __fadd_rn(l[t], l[t + off]);
    return l[0];
}

__device__ __forceinline__ uint32_t pack_bf16x2(float lo, float hi) {
    __nv_bfloat162 h = __floats2bfloat162_rn(lo, hi);   // .x = lo half
    return *reinterpret_cast<uint32_t*>(&h);
}

// ---------------------------------------------------------------- prep
__global__ void zero_kernel() { g_loss = 0.0f; }

__global__ void prep_z_kernel(const float* __restrict__ z_e) {
    int r = blockIdx.x * 256 + threadIdx.x;
    const float* zr = z_e + (size_t)r * D;
    g_sz[r] = __fadd_rn(tree32_sq(zr, 1), tree32_sq(zr + 32, 1));
}

__global__ void prep_emb_kernel(const float* __restrict__ emb) {
    int gid = blockIdx.x * 256 + threadIdx.x;
    if (gid < K * D) {
        __nv_bfloat16 h = __float2bfloat16(emb[gid]);
        g_eb[gid] = *reinterpret_cast<unsigned short*>(&h);
    }
    if (gid < K)
        g_se[gid] = __fadd_rn(tree32_sq(emb + gid * D, 1),
                              tree32_sq(emb + gid * D + 32, 1));
}

// ---------------------------------------------------------------- fused main
// Insert: in-window iff VAL <= clim; slot stale iff cv > clim. Window update
// first. On slot exhaustion, record min dropped value (cdrop) — overflow is
// decided at the END against the final threshold (recoverable). 4 slots/lane
// is load-bearing (R13: 2 slots -> fallback storm, 2.1x regression).
#define CAND_INS(S, VAL, KK)                                                   \
    do {                                                                       \
        if ((VAL) <= clim[S]) {                                                \
            if ((VAL) < crm[S]) { crm[S] = (VAL); clim[S] = (VAL) + msl[S]; }  \
            bool _ins = false;                                                 \
            _Pragma("unroll")                                                  \
            for (int _q = 0; _q < 4; _q++)                                     \
                if (!_ins && cv[S][_q] > clim[S]) {                            \
                    cv[S][_q] = (VAL); ck[S][_q] = (KK); _ins = true;          \
                }                                                              \
            if (!_ins) cdrop[S] = fminf(cdrop[S], (VAL));                      \
        }                                                                      \
    } while (0)

__global__ __launch_bounds__(256, 3)
void vq_main(const float* __restrict__ z_e, const float* __restrict__ emb,
             float* __restrict__ out, int write_idx) {
    extern __shared__ char smem[];
    __nv_bfloat16* zbf = (__nv_bfloat16*)(smem + SM_ZBF);   // [128][72]
    __nv_bfloat16* Bt  = (__nv_bfloat16*)(smem + SM_BT);    // [256][72]
    float* sse  = (float*)(smem + SM_SE);
    int*   sck  = (int*)(smem + SM_CK);                     // [128][8]
    int*   scnt = (int*)(smem + SM_CNT);                    // [128]
    float* lred = (float*)(smem + SM_LRED);
    float* zs   = (float*)(smem + SM_ZBF);                  // [128][65] stage B

    const int tid = threadIdx.x;
    const int lane = tid & 31;
    const int wid = tid >> 5;
    const int rowbase = blockIdx.x * TM;

    // ================= stage A: approx GEMM + candidate windows =============
    for (int i = tid; i < TM * 16; i += 256) {
        int r = i >> 4, c = (i & 15) * 4;
        float4 v = *(const float4*)(z_e + (size_t)(rowbase + r) * D + c);
        *(uint32_t*)&zbf[r * 72 + c]     = pack_bf16x2(v.x, v.y);
        *(uint32_t*)&zbf[r * 72 + c + 2] = pack_bf16x2(v.z, v.w);
    }
    for (int i = tid; i < K; i += 256) sse[i] = g_se[i];
    __syncthreads();

    // A fragments (held through stage A): warp = 16-row stripe
    const int r0 = wid * 16 + (lane >> 2);
    const int k0 = (lane & 3) * 2;
    uint32_t a[4][4];
    #pragma unroll
    for (int ks = 0; ks < 4; ks++) {
        a[ks][0] = *(uint32_t*)&zbf[r0 * 72 + ks * 16 + k0];
        a[ks][1] = *(uint32_t*)&zbf[(r0 + 8) * 72 + ks * 16 + k0];
        a[ks][2] = *(uint32_t*)&zbf[r0 * 72 + ks * 16 + k0 + 8];
        a[ks][3] = *(uint32_t*)&zbf[(r0 + 8) * 72 + ks * 16 + k0 + 8];
    }

    float msl[2];
    msl[0] = __fmaf_rn(sqrtf(g_sz[rowbase + r0]),     3.1e-5f, 2.0e-5f);
    msl[1] = __fmaf_rn(sqrtf(g_sz[rowbase + r0 + 8]), 3.1e-5f, 2.0e-5f);

    float cv[2][4]; int ck[2][4];
    float crm[2], clim[2], cdrop[2];
    #pragma unroll
    for (int s = 0; s < 2; s++) {
        crm[s] = 3.4e38f; clim[s] = 3.4e38f; cdrop[s] = 3.4e38f;
        #pragma unroll
        for (int q = 0; q < 4; q++) { cv[s][q] = 3.4e38f; ck[s][q] = 0; }
    }

    const uint32_t bbase =
        smem_u32(Bt) + (uint32_t)(((lane & 7) * 72 + (lane >> 3) * 8) * 2);

    for (int ch = 0; ch < NCHUNK; ch++) {
        __syncthreads();   // Bt WAR
        {
            const uint4* src = (const uint4*)g_eb + (size_t)ch * KCH * 8;
            for (int i = tid; i < KCH * 8; i += 256) {
                int rr = i >> 3, j = i & 7;
                *(uint4*)&Bt[rr * 72 + j * 8] = src[rr * 8 + j];
            }
        }
        __syncthreads();

        #pragma unroll 2
        for (int nt = 0; nt < 32; nt++) {
            uint32_t b[8];
            uint32_t addr = bbase + (uint32_t)(nt * 8 * 144);
            asm volatile(
                "ldmatrix.sync.aligned.m8n8.x4.shared.b16 {%0,%1,%2,%3}, [%4];"
                : "=r"(b[0]), "=r"(b[1]), "=r"(b[2]), "=r"(b[3]) : "r"(addr));
            asm volatile(
                "ldmatrix.sync.aligned.m8n8.x4.shared.b16 {%0,%1,%2,%3}, [%4];"
                : "=r"(b[4]), "=r"(b[5]), "=r"(b[6]), "=r"(b[7]) : "r"(addr + 64));

            float c[4] = {0.f, 0.f, 0.f, 0.f};
            #pragma unroll
            for (int ks = 0; ks < 4; ks++) {
                asm volatile(
                    "mma.sync.aligned.m16n8k16.row.col.f32.bf16.bf16.f32 "
                    "{%0,%1,%2,%3}, {%4,%5,%6,%7}, {%8,%9}, {%0,%1,%2,%3};"
                    : "+f"(c[0]), "+f"(c[1]), "+f"(c[2]), "+f"(c[3])
                    : "r"(a[ks][0]), "r"(a[ks][1]), "r"(a[ks][2]), "r"(a[ks][3]),
                      "r"(b[ks * 2]), "r"(b[ks * 2 + 1]));
            }
            const int colg = ch * KCH + nt * 8 + k0;
            float2 se2 = *(const float2*)&sse[colg];
            float v00 = fmaf(c[0], -2.0f, se2.x);
            float v01 = fmaf(c[1], -2.0f, se2.y);
            float v10 = fmaf(c[2], -2.0f, se2.x);
            float v11 = fmaf(c[3], -2.0f, se2.y);
            float m0 = fminf(v00, v01);
            float m1 = fminf(v10, v11);
            if (fminf(m0, m1) <= fmaxf(clim[0], clim[1])) {
                if (m0 <= clim[0]) {
                    CAND_INS(0, v00, colg);
                    CAND_INS(0, v01, colg + 1);
                }
                if (m1 <= clim[1]) {
                    CAND_INS(1, v10, colg);
                    CAND_INS(1, v11, colg + 1);
                }
            }
        }

        #pragma unroll
        for (int s = 0; s < 2; s++) {
            float gm = crm[s];
            gm = fminf(gm, __shfl_xor_sync(0xffffffffu, gm, 1));
            gm = fminf(gm, __shfl_xor_sync(0xffffffffu, gm, 2));
            if (gm < crm[s]) { crm[s] = gm; clim[s] = gm + msl[s]; }
        }
    }
    __syncthreads();   // stage A shared reads done (zbf/Bt become dead)

    // ---- stage z fp32 into smem (reuses zbf/Bt space), coalesced ----
    for (int i = tid; i < TM * D; i += 256) {
        zs[(i >> 6) * 65 + (i & 63)] = z_e[(size_t)rowbase * D + i];
    }

    // ---- merge candidates across the 4 lanes per row -> smem lists ----
    const int lq = lane & 3;
    #pragma unroll
    for (int s = 0; s < 2; s++) {
        float gm = crm[s];
        gm = fminf(gm, __shfl_xor_sync(0xffffffffu, gm, 1));
        gm = fminf(gm, __shfl_xor_sync(0xffffffffu, gm, 2));
        float thr = gm + msl[s];
        int cl = 0;
        #pragma unroll
        for (int q = 0; q < 4; q++) if (cv[s][q] <= thr) cl++;
        int o = (cdrop[s] <= thr) ? 1 : 0;
        o |= __shfl_xor_sync(0xffffffffu, o, 1);
        o |= __shfl_xor_sync(0xffffffffu, o, 2);
        int base = lane & ~3;
        int c0 = __shfl_sync(0xffffffffu, cl, base);
        int c1 = __shfl_sync(0xffffffffu, cl, base + 1);
        int c2 = __shfl_sync(0xffffffffu, cl, base + 2);
        int c3 = __shfl_sync(0xffffffffu, cl, base + 3);
        int tot = c0 + c1 + c2 + c3;
        int off = (lq > 0 ? c0 : 0) + (lq > 1 ? c1 : 0) + (lq > 2 ? c2 : 0);
        int lrow = wid * 16 + (lane >> 2) + s * 8;   // row within block
        if (tot > 8 || o) {
            if (lq == 0) scnt[lrow] = 10000;
        } else {
            if (lq == 0) scnt[lrow] = tot;
            int w = 0;
            #pragma unroll
            for (int q = 0; q < 4; q++)
                if (cv[s][q] <= thr) { sck[lrow * 8 + off + w] = ck[s][q]; w++; }
        }
    }
    __syncthreads();

    // ================= stage B: exact resolution (warps 0-3) ================
    int bi = 0x7fffffff;
    if (tid < TM) {
        const float* zr = &zs[tid * 65];
        const float A = g_sz[rowbase + tid];
        const int cnt = scnt[tid];
        float best = 3.4e38f;
        const bool ovf = cnt > 8;

        if (!ovf) {
            for (int i = 0; i < cnt; i++) {
                int k = sck[tid * 8 + i];
                const float* ep = emb + k * D;
                float B = 0.0f;
                #pragma unroll
                for (int d = 0; d < D; d++) B = __fmaf_rn(zr[d], ep[d], B);
                float d2 = __fadd_rn(__fsub_rn(A, __fmul_rn(2.0f, B)), sse[k]);
                if (d2 < best || (d2 == best && k < bi)) { best = d2; bi = k; }
            }
        }

        // warp-cooperative exact fallback for overflow rows (rare)
        unsigned m = __ballot_sync(0xffffffffu, ovf);
        while (m) {
            int r = __ffs(m) - 1;
            m &= m - 1;
            const float* zrr = &zs[(wid * 32 + r) * 65];
            float Ar = g_sz[rowbase + wid * 32 + r];
            float wb = 3.4e38f;
            int wbi = 0x7fffffff;
            for (int k = lane; k < K; k += 32) {
                const float* ep = emb + k * D;
                float B = 0.0f;
                #pragma unroll
                for (int d = 0; d < D; d++) B = __fmaf_rn(zrr[d], ep[d], B);
                float d2 = __fadd_rn(__fsub_rn(Ar, __fmul_rn(2.0f, B)), sse[k]);
                if (d2 < wb || (d2 == wb && k < wbi)) { wb = d2; wbi = k; }
            }
            #pragma unroll
            for (int off = 16; off >= 1; off >>= 1) {
                float ov = __shfl_xor_sync(0xffffffffu, wb, off);
                int   oi = __shfl_xor_sync(0xffffffffu, wbi, off);
                if (ov < wb || (ov == wb && oi < wbi)) { wb = ov; wbi = oi; }
            }
            if (lane == r) bi = wbi;
        }
    }
    __syncthreads();              // all candidate-list reads done
    if (tid < TM) sck[tid] = bi;  // sbidx reuses sck slot 0..127
    __syncthreads();

    // ---- coalesced gather + straight-through output + loss (all 256) ----
    float lacc = 0.0f;
    for (int i = tid; i < TM * D; i += 256) {
        int r = i >> 6, d = i & 63;
        int b = sck[r];
        float q = emb[b * D + d];
        float z = zs[r * 65 + d];
        float diff = __fsub_rn(q, z);
        out[(size_t)rowbase * D + i] = __fadd_rn(z, diff);
        lacc = __fmaf_rn(diff, diff, lacc);
    }
    if (write_idx && tid < TM)
        out[(size_t)N_ROWS * D + 1 + rowbase + tid] = (float)sck[tid];

    #pragma unroll
    for (int mm = 16; mm >= 1; mm >>= 1)
        lacc += __shfl_xor_sync(0xffffffffu, lacc, mm);
    if (lane == 0) lred[wid] = lacc;
    __syncthreads();
    if (tid == 0) {
        float s = 0.0f;
        #pragma unroll
        for (int w = 0; w < 8; w++) s += lred[w];
        atomicAdd(&g_loss, s);
    }
}

__global__ void finalize_kernel(float* __restrict__ out, int write_loss) {
    if (write_loss) {
        float m = g_loss / 8388608.0f;
        out[(size_t)N_ROWS * D] = __fadd_rn(__fmul_rn(0.25f, m), m);
    }
}

// ---------------------------------------------------------------- launch
extern "C" void kernel_launch(void* const* d_in, const int* in_sizes, int n_in,
                              void* d_out, int out_size) {
    const float* z_e = (const float*)d_in[0];
    const float* emb = (const float*)d_in[1];
    float* out = (float*)d_out;

    cudaFuncSetAttribute(vq_main, cudaFuncAttributeMaxDynamicSharedMemorySize, SMEM1);

    int write_loss = (out_size > N_ROWS * D) ? 1 : 0;
    int write_idx  = (out_size >= N_ROWS * D + 1 + N_ROWS) ? 1 : 0;

    zero_kernel<<<1, 1>>>();                                   // launch 0
    prep_z_kernel<<<N_ROWS / 256, 256>>>(z_e);                 // launch 1
    prep_emb_kernel<<<(K * D) / 256, 256>>>(emb);              // launch 2
    vq_main<<<N_ROWS / TM, 256, SMEM1>>>(z_e, emb, out, write_idx); // launch 3 (ncu)
    finalize_kernel<<<1, 1>>>(out, write_loss);                // launch 4
}